// round 6
// baseline (speedup 1.0000x reference)
#include <cuda_runtime.h>
#include <cuda_bf16.h>
#include <cuda_pipeline.h>
#include <mma.h>
#include <math.h>
#include <stdint.h>

using namespace nvcuda;

// Problem constants
#define BB 128
#define SS 256
#define EE 825
#define KP 832            // E padded to 26*32; col 825 = constant 1 (bias trick)
#define HH 600
#define HHP 608
#define G4 2400
#define G4P 2432
#define MROWS 32768
#define CTX_STRIDE 1200
#define OUT_BLK 153600
#define NIH 4800
#define NIH_PAD 4864
#define NHW_PAD 896

// ---------------------------------------------------------------------------
// Scratch (device globals)
// ---------------------------------------------------------------------------
__device__ float g_gates[(size_t)MROWS * NIH_PAD];
__device__ __nv_bfloat16 g_Ahi[(size_t)MROWS * KP];
__device__ __nv_bfloat16 g_Alo[(size_t)MROWS * KP];
__device__ __nv_bfloat16 g_A2hi[(size_t)MROWS * KP];
__device__ __nv_bfloat16 g_A2lo[(size_t)MROWS * KP];
__device__ __nv_bfloat16 g_Bhi[(size_t)NIH_PAD * KP];   // also 3*NHW_PAD=2688 rows for highway
__device__ __nv_bfloat16 g_Blo[(size_t)NIH_PAD * KP];
__device__ __nv_bfloat16 g_Whi[2 * G4P * HHP];
__device__ __nv_bfloat16 g_Wlo[2 * G4P * HHP];
__device__ __nv_bfloat16 g_hbf_hi[2][2 * BB * HHP];
__device__ __nv_bfloat16 g_hbf_lo[2][2 * BB * HHP];
__device__ float g_h[2 * BB * HH];
__device__ float g_c[2 * BB * HH];

__device__ __forceinline__ float sigm(float x) { return 1.0f / (1.0f + expf(-x)); }

// ---------------------------------------------------------------------------
// Gates GEMM (single B matrix), double-buffered cp.async, split bf16.
// ---------------------------------------------------------------------------
#define STG 40960

__global__ void __launch_bounds__(256) gemm_wmma_kernel(
        const __nv_bfloat16* __restrict__ Ahi, const __nv_bfloat16* __restrict__ Alo,
        const __nv_bfloat16* __restrict__ Bhi, const __nv_bfloat16* __restrict__ Blo,
        float* __restrict__ C, int ldc) {
    extern __shared__ char dsm[];
    const int tid = threadIdx.x;
    const int wid = tid >> 5;
    const int wm = wid >> 1;
    const int wn = wid & 1;
    const size_t m0 = (size_t)blockIdx.x * 128;
    const size_t n0 = (size_t)blockIdx.y * 128;
    const int NKB = KP / 32;

    const __nv_bfloat16* gsrc[4] = {
        Ahi + m0 * KP, Alo + m0 * KP, Bhi + n0 * KP, Blo + n0 * KP };

    wmma::fragment<wmma::accumulator, 16, 16, 16, float> acc[2][4];
    #pragma unroll
    for (int i = 0; i < 2; i++)
        #pragma unroll
        for (int j = 0; j < 4; j++)
            wmma::fill_fragment(acc[i][j], 0.0f);

    {
        char* st = dsm;
        #pragma unroll
        for (int a = 0; a < 4; a++) {
            const __nv_bfloat16* src = gsrc[a];
            #pragma unroll
            for (int r = 0; r < 2; r++) {
                int idx = tid + r * 256;
                int row = idx >> 2, seg = idx & 3;
                __pipeline_memcpy_async(st + a * 10240 + row * 80 + seg * 16,
                                        src + (size_t)row * KP + seg * 8, 16);
            }
        }
        __pipeline_commit();
    }

    for (int kb = 0; kb < NKB; kb++) {
        __pipeline_wait_prior(0);
        __syncthreads();
        if (kb + 1 < NKB) {
            char* st = dsm + ((kb + 1) & 1) * STG;
            #pragma unroll
            for (int a = 0; a < 4; a++) {
                const __nv_bfloat16* src = gsrc[a] + (kb + 1) * 32;
                #pragma unroll
                for (int r = 0; r < 2; r++) {
                    int idx = tid + r * 256;
                    int row = idx >> 2, seg = idx & 3;
                    __pipeline_memcpy_async(st + a * 10240 + row * 80 + seg * 16,
                                            src + (size_t)row * KP + seg * 8, 16);
                }
            }
            __pipeline_commit();
        }

        char* st = dsm + (kb & 1) * STG;
        typedef __nv_bfloat16 (*T40)[40];
        T40 sAh = (T40)st;
        T40 sAl = (T40)(st + 10240);
        T40 sBh = (T40)(st + 20480);
        T40 sBl = (T40)(st + 30720);

        #pragma unroll
        for (int ks = 0; ks < 2; ks++) {
            wmma::fragment<wmma::matrix_a, 16, 16, 16, __nv_bfloat16, wmma::row_major> ah[2], al[2];
            wmma::fragment<wmma::matrix_b, 16, 16, 16, __nv_bfloat16, wmma::col_major> bh[4], bl[4];
            #pragma unroll
            for (int i = 0; i < 2; i++) {
                wmma::load_matrix_sync(ah[i], &sAh[wm * 32 + i * 16][ks * 16], 40);
                wmma::load_matrix_sync(al[i], &sAl[wm * 32 + i * 16][ks * 16], 40);
            }
            #pragma unroll
            for (int j = 0; j < 4; j++) {
                wmma::load_matrix_sync(bh[j], &sBh[wn * 64 + j * 16][ks * 16], 40);
                wmma::load_matrix_sync(bl[j], &sBl[wn * 64 + j * 16][ks * 16], 40);
            }
            #pragma unroll
            for (int i = 0; i < 2; i++)
                #pragma unroll
                for (int j = 0; j < 4; j++) {
                    wmma::mma_sync(acc[i][j], ah[i], bh[j], acc[i][j]);
                    wmma::mma_sync(acc[i][j], ah[i], bl[j], acc[i][j]);
                    wmma::mma_sync(acc[i][j], al[i], bh[j], acc[i][j]);
                }
        }
        __syncthreads();
    }

    #pragma unroll
    for (int i = 0; i < 2; i++)
        #pragma unroll
        for (int j = 0; j < 4; j++)
            wmma::store_matrix_sync(&C[(m0 + wm * 32 + i * 16) * ldc + n0 + wn * 64 + j * 16],
                                    acc[i][j], ldc, wmma::mem_row_major);
}

// ---------------------------------------------------------------------------
// Fused highway layer: computes G,N,L GEMMs together (bias in col 825),
// applies gate elementwise on accumulator fragments, writes split bf16 out.
// CTA 64x128, 8 warps (wm 0..1 x wn 0..3), warp tile 32x32.
// smem per stage: A hi/lo 2x5120 + B 3 mats x hi/lo x 10240 = 71680; 2 stages.
// ---------------------------------------------------------------------------
#define HW_STAGE 71680

__global__ void __launch_bounds__(256) highway_fused_kernel(
        const __nv_bfloat16* __restrict__ Ahi_in, const __nv_bfloat16* __restrict__ Alo_in,
        __nv_bfloat16* __restrict__ Ahi_out, __nv_bfloat16* __restrict__ Alo_out) {
    extern __shared__ char dsm[];
    const int tid = threadIdx.x;
    const int wid = tid >> 5;
    const int wm = wid >> 2;        // 0..1
    const int wn = wid & 3;         // 0..3
    const size_t m0 = (size_t)blockIdx.x * 64;
    const size_t n0 = (size_t)blockIdx.y * 128;
    const int NKB = KP / 32;        // 26

    wmma::fragment<wmma::accumulator, 16, 16, 16, float> acc[3][2][2];
    #pragma unroll
    for (int m = 0; m < 3; m++)
        #pragma unroll
        for (int i = 0; i < 2; i++)
            #pragma unroll
            for (int j = 0; j < 2; j++)
                wmma::fill_fragment(acc[m][i][j], 0.0f);

    // stage fill: A = 512 tasks, B = 3072 tasks
    auto stage_fill = [&](char* st, int ko) {
        #pragma unroll
        for (int r = 0; r < 2; r++) {
            int idx = tid + r * 256;
            int row = idx >> 3, rem = idx & 7;
            int hl = rem >> 2, seg = rem & 3;
            const __nv_bfloat16* s = (hl ? Alo_in : Ahi_in) + (m0 + row) * KP + ko + seg * 8;
            __pipeline_memcpy_async(st + hl * 5120 + row * 80 + seg * 16, s, 16);
        }
        #pragma unroll
        for (int r = 0; r < 12; r++) {
            int idx = tid + r * 256;
            int arr = idx >> 9;             // 0..5 : (mat, hilo)
            int rem = idx & 511;
            int row = rem >> 2, seg = rem & 3;
            int mat = arr >> 1, hl = arr & 1;
            const __nv_bfloat16* s = (hl ? g_Blo : g_Bhi) +
                ((size_t)mat * NHW_PAD + n0 + row) * KP + ko + seg * 8;
            __pipeline_memcpy_async(st + 10240 + arr * 10240 + row * 80 + seg * 16, s, 16);
        }
        __pipeline_commit();
    };

    stage_fill(dsm, 0);

    for (int kb = 0; kb < NKB; kb++) {
        __pipeline_wait_prior(0);
        __syncthreads();
        if (kb + 1 < NKB)
            stage_fill(dsm + ((kb + 1) & 1) * HW_STAGE, (kb + 1) * 32);

        char* st = dsm + (kb & 1) * HW_STAGE;
        typedef __nv_bfloat16 (*T40)[40];
        T40 sAh = (T40)st;
        T40 sAl = (T40)(st + 5120);

        #pragma unroll
        for (int ks = 0; ks < 2; ks++) {
            wmma::fragment<wmma::matrix_a, 16, 16, 16, __nv_bfloat16, wmma::row_major> ah[2], al[2];
            #pragma unroll
            for (int i = 0; i < 2; i++) {
                wmma::load_matrix_sync(ah[i], &sAh[wm * 32 + i * 16][ks * 16], 40);
                wmma::load_matrix_sync(al[i], &sAl[wm * 32 + i * 16][ks * 16], 40);
            }
            #pragma unroll
            for (int mat = 0; mat < 3; mat++) {
                T40 sBh = (T40)(st + 10240 + (size_t)(mat * 2) * 10240);
                T40 sBl = (T40)(st + 10240 + (size_t)(mat * 2 + 1) * 10240);
                wmma::fragment<wmma::matrix_b, 16, 16, 16, __nv_bfloat16, wmma::col_major> bh[2], bl[2];
                #pragma unroll
                for (int j = 0; j < 2; j++) {
                    wmma::load_matrix_sync(bh[j], &sBh[wn * 32 + j * 16][ks * 16], 40);
                    wmma::load_matrix_sync(bl[j], &sBl[wn * 32 + j * 16][ks * 16], 40);
                }
                #pragma unroll
                for (int i = 0; i < 2; i++)
                    #pragma unroll
                    for (int j = 0; j < 2; j++) {
                        wmma::mma_sync(acc[mat][i][j], ah[i], bh[j], acc[mat][i][j]);
                        wmma::mma_sync(acc[mat][i][j], ah[i], bl[j], acc[mat][i][j]);
                        wmma::mma_sync(acc[mat][i][j], al[i], bh[j], acc[mat][i][j]);
                    }
            }
        }
        __syncthreads();
    }

    // Elementwise highway gate on fragments (same layout across same-shape frags)
    #pragma unroll
    for (int i = 0; i < 2; i++)
        #pragma unroll
        for (int j = 0; j < 2; j++) {
            #pragma unroll
            for (int e = 0; e < acc[0][i][j].num_elements; e++) {
                float G = acc[0][i][j].x[e];
                float N = acc[1][i][j].x[e];
                float L = acc[2][i][j].x[e];
                float g = sigm(G);
                acc[0][i][j].x[e] = g * fmaxf(N, 0.0f) + (1.0f - g) * L;
            }
        }

    // Stage y through smem (64x128 f32 = 32KB at dsm base)
    float (*sy)[128] = (float(*)[128])dsm;
    __syncthreads();
    #pragma unroll
    for (int i = 0; i < 2; i++)
        #pragma unroll
        for (int j = 0; j < 2; j++)
            wmma::store_matrix_sync(&sy[wm * 32 + i * 16][wn * 32 + j * 16],
                                    acc[0][i][j], 128, wmma::mem_row_major);
    __syncthreads();

    // Split-bf16 write-out with special padding columns
    #pragma unroll
    for (int r = 0; r < 32; r++) {
        int idx = tid + r * 256;
        int row = idx >> 7, col = idx & 127;
        size_t gcol = n0 + col;
        if (gcol < KP) {
            float y = sy[row][col];
            if (gcol == EE) y = 1.0f;
            else if (gcol > EE) y = 0.0f;
            __nv_bfloat16 hi = __float2bfloat16(y);
            size_t o = (m0 + row) * KP + gcol;
            Ahi_out[o] = hi;
            Alo_out[o] = __float2bfloat16(y - __bfloat162float(hi));
        }
    }
}

// ---------------------------------------------------------------------------
// Fused recurrent step (unchanged structure; bias now folded into g_gates)
// ---------------------------------------------------------------------------
#define SSTG 15360

__global__ void __launch_bounds__(128) step_fused_kernel(float* __restrict__ context, int t) {
    __shared__ char sm[2 * SSTG];
    const int tid = threadIdx.x;
    const int wid = tid >> 5;
    const int mt = blockIdx.x;
    const int hh0 = blockIdx.y * 8;
    const int d = blockIdx.z;
    const int cur = t & 1, nxt = cur ^ 1;

    const __nv_bfloat16* Ahi = g_hbf_hi[cur] + (size_t)(d * BB + mt * 64) * HHP;
    const __nv_bfloat16* Alo = g_hbf_lo[cur] + (size_t)(d * BB + mt * 64) * HHP;
    const __nv_bfloat16* Whi = g_Whi + (size_t)d * G4P * HHP;
    const __nv_bfloat16* Wlo = g_Wlo + (size_t)d * G4P * HHP;

    const int brow = tid >> 2;
    const int bseg = tid & 3;
    const size_t bsrc = (size_t)((brow >> 3) * HH + hh0 + (brow & 7)) * HHP;

    wmma::fragment<wmma::accumulator, 16, 16, 16, float> acc[2];
    wmma::fill_fragment(acc[0], 0.0f);
    wmma::fill_fragment(acc[1], 0.0f);

    const int NKB = HHP / 32;

    {
        char* st = sm;
        #pragma unroll
        for (int r = 0; r < 2; r++) {
            int idx = tid + r * 128;
            int row = idx >> 2, seg = idx & 3;
            __pipeline_memcpy_async(st + row * 80 + seg * 16,
                                    Ahi + (size_t)row * HHP + seg * 8, 16);
            __pipeline_memcpy_async(st + 5120 + row * 80 + seg * 16,
                                    Alo + (size_t)row * HHP + seg * 8, 16);
        }
        __pipeline_memcpy_async(st + 10240 + brow * 80 + bseg * 16, Whi + bsrc + bseg * 8, 16);
        __pipeline_memcpy_async(st + 12800 + brow * 80 + bseg * 16, Wlo + bsrc + bseg * 8, 16);
        __pipeline_commit();
    }

    for (int kb = 0; kb < NKB; kb++) {
        __pipeline_wait_prior(0);
        __syncthreads();
        if (kb + 1 < NKB) {
            char* st = sm + ((kb + 1) & 1) * SSTG;
            int ko = (kb + 1) * 32;
            #pragma unroll
            for (int r = 0; r < 2; r++) {
                int idx = tid + r * 128;
                int row = idx >> 2, seg = idx & 3;
                __pipeline_memcpy_async(st + row * 80 + seg * 16,
                                        Ahi + (size_t)row * HHP + ko + seg * 8, 16);
                __pipeline_memcpy_async(st + 5120 + row * 80 + seg * 16,
                                        Alo + (size_t)row * HHP + ko + seg * 8, 16);
            }
            __pipeline_memcpy_async(st + 10240 + brow * 80 + bseg * 16,
                                    Whi + bsrc + ko + bseg * 8, 16);
            __pipeline_memcpy_async(st + 12800 + brow * 80 + bseg * 16,
                                    Wlo + bsrc + ko + bseg * 8, 16);
            __pipeline_commit();
        }

        char* st = sm + (kb & 1) * SSTG;
        typedef __nv_bfloat16 (*T40)[40];
        T40 sAh = (T40)st;
        T40 sAl = (T40)(st + 5120);
        T40 sBh = (T40)(st + 10240);
        T40 sBl = (T40)(st + 12800);

        #pragma unroll
        for (int ks = 0; ks < 2; ks++) {
            wmma::fragment<wmma::matrix_a, 16, 16, 16, __nv_bfloat16, wmma::row_major> ah, al;
            wmma::fragment<wmma::matrix_b, 16, 16, 16, __nv_bfloat16, wmma::col_major> bh[2], bl[2];
            wmma::load_matrix_sync(ah, &sAh[wid * 16][ks * 16], 40);
            wmma::load_matrix_sync(al, &sAl[wid * 16][ks * 16], 40);
            #pragma unroll
            for (int j = 0; j < 2; j++) {
                wmma::load_matrix_sync(bh[j], &sBh[j * 16][ks * 16], 40);
                wmma::load_matrix_sync(bl[j], &sBl[j * 16][ks * 16], 40);
            }
            #pragma unroll
            for (int j = 0; j < 2; j++) {
                wmma::mma_sync(acc[j], ah, bh[j], acc[j]);
                wmma::mma_sync(acc[j], ah, bl[j], acc[j]);
                wmma::mma_sync(acc[j], al, bh[j], acc[j]);
            }
        }
        __syncthreads();
    }

    float (*sg)[32] = (float(*)[32])sm;
    wmma::store_matrix_sync(&sg[wid * 16][0], acc[0], 32, wmma::mem_row_major);
    wmma::store_matrix_sync(&sg[wid * 16][16], acc[1], 32, wmma::mem_row_major);
    __syncthreads();

    #pragma unroll
    for (int q = 0; q < 4; q++) {
        int e = tid + q * 128;
        int bl_ = e >> 3, hl = e & 7;
        int b = mt * 64 + bl_;
        int hh = hh0 + hl;
        size_t gx = ((size_t)b * SS + t) * NIH_PAD + d * G4;
        float gi = sg[bl_][hl]      + g_gates[gx + hh];
        float gf = sg[bl_][8 + hl]  + g_gates[gx + HH + hh];
        float gg = sg[bl_][16 + hl] + g_gates[gx + 2 * HH + hh];
        float go = sg[bl_][24 + hl] + g_gates[gx + 3 * HH + hh];
        size_t ci = (size_t)(d * BB + b) * HH + hh;
        float cold = g_c[ci];
        float cn = sigm(gf) * cold + sigm(gi) * tanhf(gg);
        float hn = sigm(go) * tanhf(cn);
        g_c[ci] = cn;
        g_h[ci] = hn;
        size_t hb = (size_t)(d * BB + b) * HHP + hh;
        __nv_bfloat16 hi = __float2bfloat16(hn);
        g_hbf_hi[nxt][hb] = hi;
        g_hbf_lo[nxt][hb] = __float2bfloat16(hn - __bfloat162float(hi));
        context[(size_t)t * OUT_BLK + (size_t)b * CTX_STRIDE + d * HH + hh] = hn;
    }
}

// ---------------------------------------------------------------------------
// Conversions / elementwise
// ---------------------------------------------------------------------------
__global__ void init_kernel(const float* __restrict__ h0, const float* __restrict__ c0) {
    int idx = blockIdx.x * blockDim.x + threadIdx.x;
    if (idx < 2 * BB * HH) { g_h[idx] = h0[idx]; g_c[idx] = c0[idx]; }
    if (idx < 2 * BB * HHP) {
        int hh = idx % HHP;
        int db = idx / HHP;
        float v = (hh < HH) ? h0[db * HH + hh] : 0.0f;
        __nv_bfloat16 hi = __float2bfloat16(v);
        __nv_bfloat16 lo = __float2bfloat16(v - __bfloat162float(hi));
        g_hbf_hi[0][idx] = hi; g_hbf_lo[0][idx] = lo;
        g_hbf_hi[1][idx] = hi; g_hbf_lo[1][idx] = lo;
    }
}

// x -> split bf16, col 825 = 1.0 (bias column), cols >825 = 0
__global__ void convA_kernel(const float* __restrict__ src) {
    int idx = blockIdx.x * blockDim.x + threadIdx.x;
    if (idx >= MROWS * KP) return;
    int col = idx % KP, row = idx / KP;
    float v;
    if (col < EE)       v = src[(size_t)row * EE + col];
    else if (col == EE) v = 1.0f;
    else                v = 0.0f;
    __nv_bfloat16 hi = __float2bfloat16(v);
    g_Ahi[idx] = hi;
    g_Alo[idx] = __float2bfloat16(v - __bfloat162float(hi));
}

// 3 highway weight mats (layer l) -> g_B, with bias at col 825
__global__ void convW3_kernel(const float* __restrict__ Wg, const float* __restrict__ bg,
                              const float* __restrict__ Wn, const float* __restrict__ bn,
                              const float* __restrict__ Wl, const float* __restrict__ bl) {
    int idx = blockIdx.x * blockDim.x + threadIdx.x;
    if (idx >= 3 * NHW_PAD * KP) return;
    int col = idx % KP;
    int rowm = idx / KP;
    int row = rowm % NHW_PAD;
    int mat = rowm / NHW_PAD;
    const float* W = (mat == 0) ? Wg : (mat == 1) ? Wn : Wl;
    const float* bs = (mat == 0) ? bg : (mat == 1) ? bn : bl;
    float v = 0.0f;
    if (row < EE) {
        if (col < EE)       v = W[(size_t)row * EE + col];
        else if (col == EE) v = bs[row];
    }
    __nv_bfloat16 hi = __float2bfloat16(v);
    g_Bhi[idx] = hi;
    g_Blo[idx] = __float2bfloat16(v - __bfloat162float(hi));
}

// W_ih -> g_B with (b_ih + b_hh) at col 825
__global__ void convWih_kernel(const float* __restrict__ W,
                               const float* __restrict__ b1, const float* __restrict__ b2) {
    int idx = blockIdx.x * blockDim.x + threadIdx.x;
    if (idx >= NIH_PAD * KP) return;
    int col = idx % KP, row = idx / KP;
    float v = 0.0f;
    if (row < NIH) {
        if (col < EE)       v = W[(size_t)row * EE + col];
        else if (col == EE) v = b1[row] + b2[row];
    }
    __nv_bfloat16 hi = __float2bfloat16(v);
    g_Bhi[idx] = hi;
    g_Blo[idx] = __float2bfloat16(v - __bfloat162float(hi));
}

__global__ void convWhh_kernel(const float* __restrict__ W) {
    int idx = blockIdx.x * blockDim.x + threadIdx.x;
    if (idx >= 2 * G4P * HHP) return;
    int col = idx % HHP;
    int rowd = idx / HHP;
    int row = rowd % G4P;
    int d = rowd / G4P;
    float v = (row < G4 && col < HH) ? W[((size_t)d * G4 + row) * HH + col] : 0.0f;
    __nv_bfloat16 hi = __float2bfloat16(v);
    g_Whi[idx] = hi;
    g_Wlo[idx] = __float2bfloat16(v - __bfloat162float(hi));
}

__global__ void finalize_kernel(float* __restrict__ out) {
    int idx = blockIdx.x * blockDim.x + threadIdx.x;
    if (idx >= OUT_BLK) return;
    const float* ctx_last = out + 4L * OUT_BLK + (long)(SS - 1) * OUT_BLK;
    float v = ctx_last[idx];
    out[idx] = v;
    out[OUT_BLK + idx] = v;
    out[2L * OUT_BLK + idx] = g_h[idx];
    out[3L * OUT_BLK + idx] = g_c[idx];
}

// ---------------------------------------------------------------------------
extern "C" void kernel_launch(void* const* d_in, const int* in_sizes, int n_in,
                              void* d_out, int out_size) {
    const float* x      = (const float*)d_in[0];
    const float* h0     = (const float*)d_in[1];
    const float* c0     = (const float*)d_in[2];
    const float* hw_Wg  = (const float*)d_in[3];
    const float* hw_bg  = (const float*)d_in[4];
    const float* hw_Wn  = (const float*)d_in[5];
    const float* hw_bn  = (const float*)d_in[6];
    const float* hw_Wl  = (const float*)d_in[7];
    const float* hw_bl  = (const float*)d_in[8];
    const float* W_ih   = (const float*)d_in[9];
    const float* W_hh   = (const float*)d_in[10];
    const float* b_ih   = (const float*)d_in[11];
    const float* b_hh   = (const float*)d_in[12];
    float* out = (float*)d_out;

    static bool attr_set = false;
    if (!attr_set) {
        cudaFuncSetAttribute(gemm_wmma_kernel,
                             cudaFuncAttributeMaxDynamicSharedMemorySize, 2 * STG);
        cudaFuncSetAttribute(highway_fused_kernel,
                             cudaFuncAttributeMaxDynamicSharedMemorySize, 2 * HW_STAGE);
        attr_set = true;
    }

    float *p_gates;
    __nv_bfloat16 *p_Ahi, *p_Alo, *p_A2hi, *p_A2lo, *p_Bhi, *p_Blo;
    cudaGetSymbolAddress((void**)&p_gates, g_gates);
    cudaGetSymbolAddress((void**)&p_Ahi, g_Ahi);
    cudaGetSymbolAddress((void**)&p_Alo, g_Alo);
    cudaGetSymbolAddress((void**)&p_A2hi, g_A2hi);
    cudaGetSymbolAddress((void**)&p_A2lo, g_A2lo);
    cudaGetSymbolAddress((void**)&p_Bhi, g_Bhi);
    cudaGetSymbolAddress((void**)&p_Blo, g_Blo);

    init_kernel<<<(2 * BB * HHP + 255) / 256, 256>>>(h0, c0);
    convWhh_kernel<<<(2 * G4P * HHP + 255) / 256, 256>>>(W_hh);
    convA_kernel<<<(MROWS * KP + 255) / 256, 256>>>(x);

    // Highway: 2 fused layers (ping-pong A buffers)
    dim3 gHW(MROWS / 64, NHW_PAD / 128);  // 512 x 7
    for (int l = 0; l < 2; l++) {
        convW3_kernel<<<(3 * NHW_PAD * KP + 255) / 256, 256>>>(
            hw_Wg + (size_t)l * EE * EE, hw_bg + l * EE,
            hw_Wn + (size_t)l * EE * EE, hw_bn + l * EE,
            hw_Wl + (size_t)l * EE * EE, hw_bl + l * EE);
        if (l == 0)
            highway_fused_kernel<<<gHW, 256, 2 * HW_STAGE>>>(p_Ahi, p_Alo, p_A2hi, p_A2lo);
        else
            highway_fused_kernel<<<gHW, 256, 2 * HW_STAGE>>>(p_A2hi, p_A2lo, p_Ahi, p_Alo);
    }

    // Input-gate precompute (bias folded via col 825)
    convWih_kernel<<<(NIH_PAD * KP + 255) / 256, 256>>>(W_ih, b_ih, b_hh);
    dim3 gGX(MROWS / 128, NIH_PAD / 128);  // 256 x 38
    gemm_wmma_kernel<<<gGX, 256, 2 * STG>>>(p_Ahi, p_Alo, p_Bhi, p_Blo, p_gates, NIH_PAD);

    // Sequential recurrence
    dim3 gST(2, HH / 8, 2);
    float* context = out + 4L * OUT_BLK;
    for (int t = 0; t < SS; t++) {
        step_fused_kernel<<<gST, 128>>>(context, t);
    }

    finalize_kernel<<<(OUT_BLK + 255) / 256, 256>>>(out);
}

// round 8
// speedup vs baseline: 1.2612x; 1.2612x over previous
#include <cuda_runtime.h>
#include <cuda_bf16.h>
#include <cuda_fp16.h>
#include <cuda_pipeline.h>
#include <mma.h>
#include <math.h>
#include <stdint.h>

using namespace nvcuda;

// Problem constants
#define BB 128
#define SS 256
#define EE 825
#define KP 832            // E padded; col 825 = constant 1 (bias trick)
#define HH 600
#define HHP 608
#define G4 2400
#define G4P 2432
#define MROWS 32768
#define CTX_STRIDE 1200
#define OUT_BLK 153600
#define NIH 4800
#define NIH_PAD 4864
#define NHW_PAD 896

// ---------------------------------------------------------------------------
// Scratch (device globals)
// ---------------------------------------------------------------------------
__device__ float g_gates[(size_t)MROWS * NIH_PAD];   // gates out; also highway raw scratch
__device__ __half g_Ah[(size_t)MROWS * KP];          // activations split fp16 hi
__device__ __half g_Al[(size_t)MROWS * KP];          // activations split fp16 lo
__device__ __half g_A2h[(size_t)MROWS * KP];
__device__ __half g_A2l[(size_t)MROWS * KP];
__device__ __half g_B[(size_t)NIH_PAD * KP];         // weights single fp16 (bias in col 825)
__device__ __nv_bfloat16 g_Whi[2 * G4P * HHP];       // recurrence weights split bf16
__device__ __nv_bfloat16 g_Wlo[2 * G4P * HHP];
__device__ __nv_bfloat16 g_hbf_hi[2][2 * BB * HHP];
__device__ __nv_bfloat16 g_hbf_lo[2][2 * BB * HHP];
__device__ float g_h[2 * BB * HH];
__device__ float g_c[2 * BB * HH];

__device__ __forceinline__ float sigm(float x) { return 1.0f / (1.0f + expf(-x)); }

// ---------------------------------------------------------------------------
// Big GEMM: C = (Ah + Al) @ B^T, fp16 2-product, fp32 accum.
// 128x128 CTA tile, 8 warps (wm 0..3 x wn 0..1), warp 32x64.
// Stage = 3 mats x 128 rows x 80B = 30720B; 2 stages cp.async ping-pong.
// ---------------------------------------------------------------------------
#define STG 30720

__global__ void __launch_bounds__(256) gemm_fp16_kernel(
        const __half* __restrict__ Ah, const __half* __restrict__ Al,
        const __half* __restrict__ B,
        float* __restrict__ C, int ldc) {
    extern __shared__ char dsm[];
    const int tid = threadIdx.x;
    const int wid = tid >> 5;
    const int wm = wid >> 1;        // 0..3
    const int wn = wid & 1;         // 0..1
    const size_t m0 = (size_t)blockIdx.x * 128;
    const size_t n0 = (size_t)blockIdx.y * 128;
    const int NKB = KP / 32;        // 26

    const __half* gsrc[3] = { Ah + m0 * KP, Al + m0 * KP, B + n0 * KP };

    wmma::fragment<wmma::accumulator, 16, 16, 16, float> acc[2][4];
    #pragma unroll
    for (int i = 0; i < 2; i++)
        #pragma unroll
        for (int j = 0; j < 4; j++)
            wmma::fill_fragment(acc[i][j], 0.0f);

    auto stage_fill = [&](char* st, int ko) {
        #pragma unroll
        for (int r = 0; r < 6; r++) {
            int idx = tid + r * 256;        // 0..1535
            int arr = idx >> 9;             // 0..2
            int rem = idx & 511;
            int row = rem >> 2, seg = rem & 3;
            __pipeline_memcpy_async(st + arr * 10240 + row * 80 + seg * 16,
                                    gsrc[arr] + (size_t)row * KP + ko + seg * 8, 16);
        }
        __pipeline_commit();
    };

    stage_fill(dsm, 0);

    for (int kb = 0; kb < NKB; kb++) {
        __pipeline_wait_prior(0);
        __syncthreads();
        if (kb + 1 < NKB)
            stage_fill(dsm + ((kb + 1) & 1) * STG, (kb + 1) * 32);

        char* st = dsm + (kb & 1) * STG;
        typedef __half (*T40)[40];
        T40 sAh = (T40)st;
        T40 sAl = (T40)(st + 10240);
        T40 sB  = (T40)(st + 20480);

        #pragma unroll
        for (int ks = 0; ks < 2; ks++) {
            wmma::fragment<wmma::matrix_a, 16, 16, 16, __half, wmma::row_major> ah[2], al[2];
            wmma::fragment<wmma::matrix_b, 16, 16, 16, __half, wmma::col_major> b[4];
            #pragma unroll
            for (int i = 0; i < 2; i++) {
                wmma::load_matrix_sync(ah[i], &sAh[wm * 32 + i * 16][ks * 16], 40);
                wmma::load_matrix_sync(al[i], &sAl[wm * 32 + i * 16][ks * 16], 40);
            }
            #pragma unroll
            for (int j = 0; j < 4; j++)
                wmma::load_matrix_sync(b[j], &sB[wn * 64 + j * 16][ks * 16], 40);
            #pragma unroll
            for (int i = 0; i < 2; i++)
                #pragma unroll
                for (int j = 0; j < 4; j++) {
                    wmma::mma_sync(acc[i][j], ah[i], b[j], acc[i][j]);
                    wmma::mma_sync(acc[i][j], al[i], b[j], acc[i][j]);
                }
        }
        __syncthreads();
    }

    #pragma unroll
    for (int i = 0; i < 2; i++)
        #pragma unroll
        for (int j = 0; j < 4; j++)
            wmma::store_matrix_sync(&C[(m0 + wm * 32 + i * 16) * ldc + n0 + wn * 64 + j * 16],
                                    acc[i][j], ldc, wmma::mem_row_major);
}

// ---------------------------------------------------------------------------
// Fused recurrent step: bf16 3-product GEMM + LSTM cell (unchanged from R5/R6)
// ---------------------------------------------------------------------------
#define SSTG 15360

__global__ void __launch_bounds__(128) step_fused_kernel(float* __restrict__ context, int t) {
    __shared__ char sm[2 * SSTG];
    const int tid = threadIdx.x;
    const int wid = tid >> 5;
    const int mt = blockIdx.x;
    const int hh0 = blockIdx.y * 8;
    const int d = blockIdx.z;
    const int cur = t & 1, nxt = cur ^ 1;

    const __nv_bfloat16* Ahi = g_hbf_hi[cur] + (size_t)(d * BB + mt * 64) * HHP;
    const __nv_bfloat16* Alo = g_hbf_lo[cur] + (size_t)(d * BB + mt * 64) * HHP;
    const __nv_bfloat16* Whi = g_Whi + (size_t)d * G4P * HHP;
    const __nv_bfloat16* Wlo = g_Wlo + (size_t)d * G4P * HHP;

    const int brow = tid >> 2;
    const int bseg = tid & 3;
    const size_t bsrc = (size_t)((brow >> 3) * HH + hh0 + (brow & 7)) * HHP;

    wmma::fragment<wmma::accumulator, 16, 16, 16, float> acc[2];
    wmma::fill_fragment(acc[0], 0.0f);
    wmma::fill_fragment(acc[1], 0.0f);

    const int NKB = HHP / 32;

    {
        char* st = sm;
        #pragma unroll
        for (int r = 0; r < 2; r++) {
            int idx = tid + r * 128;
            int row = idx >> 2, seg = idx & 3;
            __pipeline_memcpy_async(st + row * 80 + seg * 16,
                                    Ahi + (size_t)row * HHP + seg * 8, 16);
            __pipeline_memcpy_async(st + 5120 + row * 80 + seg * 16,
                                    Alo + (size_t)row * HHP + seg * 8, 16);
        }
        __pipeline_memcpy_async(st + 10240 + brow * 80 + bseg * 16, Whi + bsrc + bseg * 8, 16);
        __pipeline_memcpy_async(st + 12800 + brow * 80 + bseg * 16, Wlo + bsrc + bseg * 8, 16);
        __pipeline_commit();
    }

    for (int kb = 0; kb < NKB; kb++) {
        __pipeline_wait_prior(0);
        __syncthreads();
        if (kb + 1 < NKB) {
            char* st = sm + ((kb + 1) & 1) * SSTG;
            int ko = (kb + 1) * 32;
            #pragma unroll
            for (int r = 0; r < 2; r++) {
                int idx = tid + r * 128;
                int row = idx >> 2, seg = idx & 3;
                __pipeline_memcpy_async(st + row * 80 + seg * 16,
                                        Ahi + (size_t)row * HHP + ko + seg * 8, 16);
                __pipeline_memcpy_async(st + 5120 + row * 80 + seg * 16,
                                        Alo + (size_t)row * HHP + ko + seg * 8, 16);
            }
            __pipeline_memcpy_async(st + 10240 + brow * 80 + bseg * 16,
                                    Whi + bsrc + ko + bseg * 8, 16);
            __pipeline_memcpy_async(st + 12800 + brow * 80 + bseg * 16,
                                    Wlo + bsrc + ko + bseg * 8, 16);
            __pipeline_commit();
        }

        char* st = sm + (kb & 1) * SSTG;
        typedef __nv_bfloat16 (*T40)[40];
        T40 sAh = (T40)st;
        T40 sAl = (T40)(st + 5120);
        T40 sBh = (T40)(st + 10240);
        T40 sBl = (T40)(st + 12800);

        #pragma unroll
        for (int ks = 0; ks < 2; ks++) {
            wmma::fragment<wmma::matrix_a, 16, 16, 16, __nv_bfloat16, wmma::row_major> ah, al;
            wmma::fragment<wmma::matrix_b, 16, 16, 16, __nv_bfloat16, wmma::col_major> bh[2], bl[2];
            wmma::load_matrix_sync(ah, &sAh[wid * 16][ks * 16], 40);
            wmma::load_matrix_sync(al, &sAl[wid * 16][ks * 16], 40);
            #pragma unroll
            for (int j = 0; j < 2; j++) {
                wmma::load_matrix_sync(bh[j], &sBh[j * 16][ks * 16], 40);
                wmma::load_matrix_sync(bl[j], &sBl[j * 16][ks * 16], 40);
            }
            #pragma unroll
            for (int j = 0; j < 2; j++) {
                wmma::mma_sync(acc[j], ah, bh[j], acc[j]);
                wmma::mma_sync(acc[j], ah, bl[j], acc[j]);
                wmma::mma_sync(acc[j], al, bh[j], acc[j]);
            }
        }
        __syncthreads();
    }

    float (*sg)[32] = (float(*)[32])sm;
    wmma::store_matrix_sync(&sg[wid * 16][0], acc[0], 32, wmma::mem_row_major);
    wmma::store_matrix_sync(&sg[wid * 16][16], acc[1], 32, wmma::mem_row_major);
    __syncthreads();

    #pragma unroll
    for (int q = 0; q < 4; q++) {
        int e = tid + q * 128;
        int bl_ = e >> 3, hl = e & 7;
        int b = mt * 64 + bl_;
        int hh = hh0 + hl;
        size_t gx = ((size_t)b * SS + t) * NIH_PAD + d * G4;
        float gi = sg[bl_][hl]      + g_gates[gx + hh];
        float gf = sg[bl_][8 + hl]  + g_gates[gx + HH + hh];
        float gg = sg[bl_][16 + hl] + g_gates[gx + 2 * HH + hh];
        float go = sg[bl_][24 + hl] + g_gates[gx + 3 * HH + hh];
        size_t ci = (size_t)(d * BB + b) * HH + hh;
        float cold = g_c[ci];
        float cn = sigm(gf) * cold + sigm(gi) * tanhf(gg);
        float hn = sigm(go) * tanhf(cn);
        g_c[ci] = cn;
        g_h[ci] = hn;
        size_t hb = (size_t)(d * BB + b) * HHP + hh;
        __nv_bfloat16 hi = __float2bfloat16(hn);
        g_hbf_hi[nxt][hb] = hi;
        g_hbf_lo[nxt][hb] = __float2bfloat16(hn - __bfloat162float(hi));
        context[(size_t)t * OUT_BLK + (size_t)b * CTX_STRIDE + d * HH + hh] = hn;
    }
}

// ---------------------------------------------------------------------------
// Conversions / elementwise
// ---------------------------------------------------------------------------
__global__ void init_kernel(const float* __restrict__ h0, const float* __restrict__ c0) {
    int idx = blockIdx.x * blockDim.x + threadIdx.x;
    if (idx < 2 * BB * HH) { g_h[idx] = h0[idx]; g_c[idx] = c0[idx]; }
    if (idx < 2 * BB * HHP) {
        int hh = idx % HHP;
        int db = idx / HHP;
        float v = (hh < HH) ? h0[db * HH + hh] : 0.0f;
        __nv_bfloat16 hi = __float2bfloat16(v);
        __nv_bfloat16 lo = __float2bfloat16(v - __bfloat162float(hi));
        g_hbf_hi[0][idx] = hi; g_hbf_lo[0][idx] = lo;
        g_hbf_hi[1][idx] = hi; g_hbf_lo[1][idx] = lo;
    }
}

// x -> split fp16, col 825 = 1.0 (bias column), cols > 825 = 0
__global__ void convA_kernel(const float* __restrict__ src) {
    int idx = blockIdx.x * blockDim.x + threadIdx.x;
    if (idx >= MROWS * KP) return;
    int col = idx % KP, row = idx / KP;
    float v;
    if (col < EE)       v = src[(size_t)row * EE + col];
    else if (col == EE) v = 1.0f;
    else                v = 0.0f;
    __half hi = __float2half(v);
    g_Ah[idx] = hi;
    g_Al[idx] = __float2half(v - __half2float(hi));
}

// 3 highway weight mats (layer l) -> g_B single fp16, bias at col 825
__global__ void convW3_kernel(const float* __restrict__ Wg, const float* __restrict__ bg,
                              const float* __restrict__ Wn, const float* __restrict__ bn,
                              const float* __restrict__ Wl, const float* __restrict__ bl) {
    int idx = blockIdx.x * blockDim.x + threadIdx.x;
    if (idx >= 3 * NHW_PAD * KP) return;
    int col = idx % KP;
    int rowm = idx / KP;
    int row = rowm % NHW_PAD;
    int mat = rowm / NHW_PAD;
    const float* W = (mat == 0) ? Wg : (mat == 1) ? Wn : Wl;
    const float* bs = (mat == 0) ? bg : (mat == 1) ? bn : bl;
    float v = 0.0f;
    if (row < EE) {
        if (col < EE)       v = W[(size_t)row * EE + col];
        else if (col == EE) v = bs[row];
    }
    g_B[idx] = __float2half(v);
}

// W_ih -> g_B single fp16, (b_ih + b_hh) at col 825
__global__ void convWih_kernel(const float* __restrict__ W,
                               const float* __restrict__ b1, const float* __restrict__ b2) {
    int idx = blockIdx.x * blockDim.x + threadIdx.x;
    if (idx >= NIH_PAD * KP) return;
    int col = idx % KP, row = idx / KP;
    float v = 0.0f;
    if (row < NIH) {
        if (col < EE)       v = W[(size_t)row * EE + col];
        else if (col == EE) v = b1[row] + b2[row];
    }
    g_B[idx] = __float2half(v);
}

__global__ void convWhh_kernel(const float* __restrict__ W) {
    int idx = blockIdx.x * blockDim.x + threadIdx.x;
    if (idx >= 2 * G4P * HHP) return;
    int col = idx % HHP;
    int rowd = idx / HHP;
    int row = rowd % G4P;
    int d = rowd / G4P;
    float v = (row < G4 && col < HH) ? W[((size_t)d * G4 + row) * HH + col] : 0.0f;
    __nv_bfloat16 hi = __float2bfloat16(v);
    g_Whi[idx] = hi;
    g_Wlo[idx] = __float2bfloat16(v - __bfloat162float(hi));
}

// highway combine: raw G/N/L pre-biased; y -> split fp16 out (ping-pong)
__global__ void combine_kernel(const float* __restrict__ rawG, const float* __restrict__ rawN,
                               const float* __restrict__ rawL,
                               __half* __restrict__ Aout_h, __half* __restrict__ Aout_l) {
    int idx = blockIdx.x * blockDim.x + threadIdx.x;
    if (idx >= MROWS * KP) return;
    int col = idx % KP, row = idx / KP;
    float y;
    if (col < EE) {
        size_t r = (size_t)row * NHW_PAD + col;
        float gate = sigm(rawG[r]);
        float nl   = fmaxf(rawN[r], 0.0f);
        float ln   = rawL[r];
        y = gate * nl + (1.0f - gate) * ln;
    } else if (col == EE) y = 1.0f;
    else y = 0.0f;
    __half hi = __float2half(y);
    Aout_h[idx] = hi;
    Aout_l[idx] = __float2half(y - __half2float(hi));
}

__global__ void finalize_kernel(float* __restrict__ out) {
    int idx = blockIdx.x * blockDim.x + threadIdx.x;
    if (idx >= OUT_BLK) return;
    const float* ctx_last = out + 4L * OUT_BLK + (long)(SS - 1) * OUT_BLK;
    float v = ctx_last[idx];
    out[idx] = v;
    out[OUT_BLK + idx] = v;
    out[2L * OUT_BLK + idx] = g_h[idx];
    out[3L * OUT_BLK + idx] = g_c[idx];
}

// ---------------------------------------------------------------------------
extern "C" void kernel_launch(void* const* d_in, const int* in_sizes, int n_in,
                              void* d_out, int out_size) {
    const float* x      = (const float*)d_in[0];
    const float* h0     = (const float*)d_in[1];
    const float* c0     = (const float*)d_in[2];
    const float* hw_Wg  = (const float*)d_in[3];
    const float* hw_bg  = (const float*)d_in[4];
    const float* hw_Wn  = (const float*)d_in[5];
    const float* hw_bn  = (const float*)d_in[6];
    const float* hw_Wl  = (const float*)d_in[7];
    const float* hw_bl  = (const float*)d_in[8];
    const float* W_ih   = (const float*)d_in[9];
    const float* W_hh   = (const float*)d_in[10];
    const float* b_ih   = (const float*)d_in[11];
    const float* b_hh   = (const float*)d_in[12];
    float* out = (float*)d_out;

    static bool attr_set = false;
    if (!attr_set) {
        cudaFuncSetAttribute(gemm_fp16_kernel,
                             cudaFuncAttributeMaxDynamicSharedMemorySize, 2 * STG);
        attr_set = true;
    }

    float *p_gates;
    __half *p_Ah, *p_Al, *p_A2h, *p_A2l, *p_B;
    cudaGetSymbolAddress((void**)&p_gates, g_gates);
    cudaGetSymbolAddress((void**)&p_Ah, g_Ah);
    cudaGetSymbolAddress((void**)&p_Al, g_Al);
    cudaGetSymbolAddress((void**)&p_A2h, g_A2h);
    cudaGetSymbolAddress((void**)&p_A2l, g_A2l);
    cudaGetSymbolAddress((void**)&p_B, g_B);

    init_kernel<<<(2 * BB * HHP + 255) / 256, 256>>>(h0, c0);
    convWhh_kernel<<<(2 * G4P * HHP + 255) / 256, 256>>>(W_hh);
    convA_kernel<<<(MROWS * KP + 255) / 256, 256>>>(x);

    // Highway: 2 layers, 3 separate GEMMs + combine (R5 structure, fp16 2-product)
    float* raw[3] = { p_gates,
                      p_gates + (size_t)MROWS * NHW_PAD,
                      p_gates + 2 * (size_t)MROWS * NHW_PAD };
    dim3 gHW(MROWS / 128, NHW_PAD / 128);  // 256 x 7
    for (int l = 0; l < 2; l++) {
        convW3_kernel<<<(3 * NHW_PAD * KP + 255) / 256, 256>>>(
            hw_Wg + (size_t)l * EE * EE, hw_bg + l * EE,
            hw_Wn + (size_t)l * EE * EE, hw_bn + l * EE,
            hw_Wl + (size_t)l * EE * EE, hw_bl + l * EE);
        const __half* Ah = (l == 0) ? p_Ah : p_A2h;
        const __half* Al = (l == 0) ? p_Al : p_A2l;
        for (int w = 0; w < 3; w++)
            gemm_fp16_kernel<<<gHW, 256, 2 * STG>>>(Ah, Al,
                p_B + (size_t)w * NHW_PAD * KP, raw[w], NHW_PAD);
        if (l == 0)
            combine_kernel<<<(MROWS * KP + 255) / 256, 256>>>(raw[0], raw[1], raw[2], p_A2h, p_A2l);
        else
            combine_kernel<<<(MROWS * KP + 255) / 256, 256>>>(raw[0], raw[1], raw[2], p_Ah, p_Al);
    }

    // Input-gate precompute (bias folded via col 825)
    convWih_kernel<<<(NIH_PAD * KP + 255) / 256, 256>>>(W_ih, b_ih, b_hh);
    dim3 gGX(MROWS / 128, NIH_PAD / 128);  // 256 x 38
    gemm_fp16_kernel<<<gGX, 256, 2 * STG>>>(p_Ah, p_Al, p_B, p_gates, NIH_PAD);

    // Sequential recurrence
    dim3 gST(2, HH / 8, 2);
    float* context = out + 4L * OUT_BLK;
    for (int t = 0; t < SS; t++) {
        step_fused_kernel<<<gST, 128>>>(context, t);
    }

    finalize_kernel<<<(OUT_BLK + 255) / 256, 256>>>(out);
}

// round 10
// speedup vs baseline: 1.5002x; 1.1895x over previous
#include <cuda_runtime.h>
#include <cuda_bf16.h>
#include <cuda_fp16.h>
#include <cuda_pipeline.h>
#include <mma.h>
#include <math.h>
#include <stdint.h>

using namespace nvcuda;

// Problem constants
#define BB 128
#define SS 256
#define EE 825
#define KP 832            // E padded; col 825 = constant 1 (bias trick)
#define HH 600
#define HHP 608
#define G4 2400
#define G4P 2432
#define MROWS 32768
#define CTX_STRIDE 1200
#define OUT_BLK 153600
#define NIH 4800
#define NIH_PAD 4864
#define NHW_PAD 896

// ---------------------------------------------------------------------------
// Scratch (device globals)
// ---------------------------------------------------------------------------
__device__ float g_gates[(size_t)MROWS * NIH_PAD];   // gates out; also highway raw scratch
__device__ __half g_A1[(size_t)MROWS * KP];          // activations fp16 (ping)
__device__ __half g_A2[(size_t)MROWS * KP];          // activations fp16 (pong)
__device__ __half g_B[(size_t)NIH_PAD * KP];         // weights fp16 (bias in col 825)
__device__ __nv_bfloat16 g_Whi[2 * G4P * HHP];       // recurrence weights split bf16
__device__ __nv_bfloat16 g_Wlo[2 * G4P * HHP];
__device__ __nv_bfloat16 g_hbf_hi[2][2 * BB * HHP];
__device__ __nv_bfloat16 g_hbf_lo[2][2 * BB * HHP];
__device__ float g_h[2 * BB * HH];
__device__ float g_c[2 * BB * HH];

__device__ __forceinline__ float sigm(float x) { return 1.0f / (1.0f + expf(-x)); }

// ---------------------------------------------------------------------------
// Big GEMM: C = A @ B^T, pure fp16, fp32 accum.
// 128x128 CTA tile, 8 warps (wm 0..3 x wn 0..1), warp 32x64.
// Stage = 2 mats x 128 rows x 80B = 20480B; 3-stage cp.async ring.
// ---------------------------------------------------------------------------
#define STG 20480

__global__ void __launch_bounds__(256) gemm_fp16_kernel(
        const __half* __restrict__ A, const __half* __restrict__ B,
        float* __restrict__ C, int ldc) {
    extern __shared__ char dsm[];
    const int tid = threadIdx.x;
    const int wid = tid >> 5;
    const int wm = wid >> 1;        // 0..3
    const int wn = wid & 1;         // 0..1
    const size_t m0 = (size_t)blockIdx.x * 128;
    const size_t n0 = (size_t)blockIdx.y * 128;
    const int NKB = KP / 32;        // 26

    const __half* gA = A + m0 * KP;
    const __half* gB = B + n0 * KP;

    wmma::fragment<wmma::accumulator, 16, 16, 16, float> acc[2][4];
    #pragma unroll
    for (int i = 0; i < 2; i++)
        #pragma unroll
        for (int j = 0; j < 4; j++)
            wmma::fill_fragment(acc[i][j], 0.0f);

    auto stage_fill = [&](int stg, int ko) {
        char* st = dsm + stg * STG;
        #pragma unroll
        for (int r = 0; r < 4; r++) {
            int idx = tid + r * 256;        // 0..1023
            int arr = idx >> 9;             // 0..1
            int rem = idx & 511;
            int row = rem >> 2, seg = rem & 3;
            const __half* src = (arr ? gB : gA) + (size_t)row * KP + ko + seg * 8;
            __pipeline_memcpy_async(st + arr * 10240 + row * 80 + seg * 16, src, 16);
        }
        __pipeline_commit();
    };

    stage_fill(0, 0);
    stage_fill(1, 32);

    int stg = 0;
    for (int kb = 0; kb < NKB; kb++) {
        __pipeline_wait_prior(1);
        __syncthreads();
        if (kb + 2 < NKB)
            stage_fill((stg + 2) % 3, (kb + 2) * 32);

        char* st = dsm + stg * STG;
        typedef __half (*T40)[40];
        T40 sA = (T40)st;
        T40 sB = (T40)(st + 10240);

        #pragma unroll
        for (int ks = 0; ks < 2; ks++) {
            wmma::fragment<wmma::matrix_a, 16, 16, 16, __half, wmma::row_major> a[2];
            wmma::fragment<wmma::matrix_b, 16, 16, 16, __half, wmma::col_major> b[4];
            #pragma unroll
            for (int i = 0; i < 2; i++)
                wmma::load_matrix_sync(a[i], &sA[wm * 32 + i * 16][ks * 16], 40);
            #pragma unroll
            for (int j = 0; j < 4; j++)
                wmma::load_matrix_sync(b[j], &sB[wn * 64 + j * 16][ks * 16], 40);
            #pragma unroll
            for (int i = 0; i < 2; i++)
                #pragma unroll
                for (int j = 0; j < 4; j++)
                    wmma::mma_sync(acc[i][j], a[i], b[j], acc[i][j]);
        }
        stg = (stg + 1) % 3;
    }

    #pragma unroll
    for (int i = 0; i < 2; i++)
        #pragma unroll
        for (int j = 0; j < 4; j++)
            wmma::store_matrix_sync(&C[(m0 + wm * 32 + i * 16) * ldc + n0 + wn * 64 + j * 16],
                                    acc[i][j], ldc, wmma::mem_row_major);
}

// ---------------------------------------------------------------------------
// Fused recurrent step: bf16 3-product GEMM + LSTM cell (unchanged)
// ---------------------------------------------------------------------------
#define SSTG 15360

__global__ void __launch_bounds__(128) step_fused_kernel(float* __restrict__ context, int t) {
    __shared__ char sm[2 * SSTG];
    const int tid = threadIdx.x;
    const int wid = tid >> 5;
    const int mt = blockIdx.x;
    const int hh0 = blockIdx.y * 8;
    const int d = blockIdx.z;
    const int cur = t & 1, nxt = cur ^ 1;

    const __nv_bfloat16* Ahi = g_hbf_hi[cur] + (size_t)(d * BB + mt * 64) * HHP;
    const __nv_bfloat16* Alo = g_hbf_lo[cur] + (size_t)(d * BB + mt * 64) * HHP;
    const __nv_bfloat16* Whi = g_Whi + (size_t)d * G4P * HHP;
    const __nv_bfloat16* Wlo = g_Wlo + (size_t)d * G4P * HHP;

    const int brow = tid >> 2;
    const int bseg = tid & 3;
    const size_t bsrc = (size_t)((brow >> 3) * HH + hh0 + (brow & 7)) * HHP;

    wmma::fragment<wmma::accumulator, 16, 16, 16, float> acc[2];
    wmma::fill_fragment(acc[0], 0.0f);
    wmma::fill_fragment(acc[1], 0.0f);

    const int NKB = HHP / 32;

    {
        char* st = sm;
        #pragma unroll
        for (int r = 0; r < 2; r++) {
            int idx = tid + r * 128;
            int row = idx >> 2, seg = idx & 3;
            __pipeline_memcpy_async(st + row * 80 + seg * 16,
                                    Ahi + (size_t)row * HHP + seg * 8, 16);
            __pipeline_memcpy_async(st + 5120 + row * 80 + seg * 16,
                                    Alo + (size_t)row * HHP + seg * 8, 16);
        }
        __pipeline_memcpy_async(st + 10240 + brow * 80 + bseg * 16, Whi + bsrc + bseg * 8, 16);
        __pipeline_memcpy_async(st + 12800 + brow * 80 + bseg * 16, Wlo + bsrc + bseg * 8, 16);
        __pipeline_commit();
    }

    for (int kb = 0; kb < NKB; kb++) {
        __pipeline_wait_prior(0);
        __syncthreads();
        if (kb + 1 < NKB) {
            char* st = sm + ((kb + 1) & 1) * SSTG;
            int ko = (kb + 1) * 32;
            #pragma unroll
            for (int r = 0; r < 2; r++) {
                int idx = tid + r * 128;
                int row = idx >> 2, seg = idx & 3;
                __pipeline_memcpy_async(st + row * 80 + seg * 16,
                                        Ahi + (size_t)row * HHP + ko + seg * 8, 16);
                __pipeline_memcpy_async(st + 5120 + row * 80 + seg * 16,
                                        Alo + (size_t)row * HHP + ko + seg * 8, 16);
            }
            __pipeline_memcpy_async(st + 10240 + brow * 80 + bseg * 16,
                                    Whi + bsrc + ko + bseg * 8, 16);
            __pipeline_memcpy_async(st + 12800 + brow * 80 + bseg * 16,
                                    Wlo + bsrc + ko + bseg * 8, 16);
            __pipeline_commit();
        }

        char* st = sm + (kb & 1) * SSTG;
        typedef __nv_bfloat16 (*T40)[40];
        T40 sAh = (T40)st;
        T40 sAl = (T40)(st + 5120);
        T40 sBh = (T40)(st + 10240);
        T40 sBl = (T40)(st + 12800);

        #pragma unroll
        for (int ks = 0; ks < 2; ks++) {
            wmma::fragment<wmma::matrix_a, 16, 16, 16, __nv_bfloat16, wmma::row_major> ah, al;
            wmma::fragment<wmma::matrix_b, 16, 16, 16, __nv_bfloat16, wmma::col_major> bh[2], bl[2];
            wmma::load_matrix_sync(ah, &sAh[wid * 16][ks * 16], 40);
            wmma::load_matrix_sync(al, &sAl[wid * 16][ks * 16], 40);
            #pragma unroll
            for (int j = 0; j < 2; j++) {
                wmma::load_matrix_sync(bh[j], &sBh[j * 16][ks * 16], 40);
                wmma::load_matrix_sync(bl[j], &sBl[j * 16][ks * 16], 40);
            }
            #pragma unroll
            for (int j = 0; j < 2; j++) {
                wmma::mma_sync(acc[j], ah, bh[j], acc[j]);
                wmma::mma_sync(acc[j], ah, bl[j], acc[j]);
                wmma::mma_sync(acc[j], al, bh[j], acc[j]);
            }
        }
        __syncthreads();
    }

    float (*sg)[32] = (float(*)[32])sm;
    wmma::store_matrix_sync(&sg[wid * 16][0], acc[0], 32, wmma::mem_row_major);
    wmma::store_matrix_sync(&sg[wid * 16][16], acc[1], 32, wmma::mem_row_major);
    __syncthreads();

    #pragma unroll
    for (int q = 0; q < 4; q++) {
        int e = tid + q * 128;
        int bl_ = e >> 3, hl = e & 7;
        int b = mt * 64 + bl_;
        int hh = hh0 + hl;
        size_t gx = ((size_t)b * SS + t) * NIH_PAD + d * G4;
        float gi = sg[bl_][hl]      + g_gates[gx + hh];
        float gf = sg[bl_][8 + hl]  + g_gates[gx + HH + hh];
        float gg = sg[bl_][16 + hl] + g_gates[gx + 2 * HH + hh];
        float go = sg[bl_][24 + hl] + g_gates[gx + 3 * HH + hh];
        size_t ci = (size_t)(d * BB + b) * HH + hh;
        float cold = g_c[ci];
        float cn = sigm(gf) * cold + sigm(gi) * tanhf(gg);
        float hn = sigm(go) * tanhf(cn);
        g_c[ci] = cn;
        g_h[ci] = hn;
        size_t hb = (size_t)(d * BB + b) * HHP + hh;
        __nv_bfloat16 hi = __float2bfloat16(hn);
        g_hbf_hi[nxt][hb] = hi;
        g_hbf_lo[nxt][hb] = __float2bfloat16(hn - __bfloat162float(hi));
        context[(size_t)t * OUT_BLK + (size_t)b * CTX_STRIDE + d * HH + hh] = hn;
    }
}

// ---------------------------------------------------------------------------
// Conversions / elementwise
// ---------------------------------------------------------------------------
__global__ void init_kernel(const float* __restrict__ h0, const float* __restrict__ c0) {
    int idx = blockIdx.x * blockDim.x + threadIdx.x;
    if (idx < 2 * BB * HH) { g_h[idx] = h0[idx]; g_c[idx] = c0[idx]; }
    if (idx < 2 * BB * HHP) {
        int hh = idx % HHP;
        int db = idx / HHP;
        float v = (hh < HH) ? h0[db * HH + hh] : 0.0f;
        __nv_bfloat16 hi = __float2bfloat16(v);
        __nv_bfloat16 lo = __float2bfloat16(v - __bfloat162float(hi));
        g_hbf_hi[0][idx] = hi; g_hbf_lo[0][idx] = lo;
        g_hbf_hi[1][idx] = hi; g_hbf_lo[1][idx] = lo;
    }
}

// x -> fp16, col 825 = 1.0 (bias column), cols > 825 = 0
__global__ void convA_kernel(const float* __restrict__ src) {
    int idx = blockIdx.x * blockDim.x + threadIdx.x;
    if (idx >= MROWS * KP) return;
    int col = idx % KP, row = idx / KP;
    float v;
    if (col < EE)       v = src[(size_t)row * EE + col];
    else if (col == EE) v = 1.0f;
    else                v = 0.0f;
    g_A1[idx] = __float2half(v);
}

// 3 highway weight mats (layer l) -> g_B fp16, bias at col 825
__global__ void convW3_kernel(const float* __restrict__ Wg, const float* __restrict__ bg,
                              const float* __restrict__ Wn, const float* __restrict__ bn,
                              const float* __restrict__ Wl, const float* __restrict__ bl) {
    int idx = blockIdx.x * blockDim.x + threadIdx.x;
    if (idx >= 3 * NHW_PAD * KP) return;
    int col = idx % KP;
    int rowm = idx / KP;
    int row = rowm % NHW_PAD;
    int mat = rowm / NHW_PAD;
    const float* W = (mat == 0) ? Wg : (mat == 1) ? Wn : Wl;
    const float* bs = (mat == 0) ? bg : (mat == 1) ? bn : bl;
    float v = 0.0f;
    if (row < EE) {
        if (col < EE)       v = W[(size_t)row * EE + col];
        else if (col == EE) v = bs[row];
    }
    g_B[idx] = __float2half(v);
}

// W_ih -> g_B fp16, (b_ih + b_hh) at col 825
__global__ void convWih_kernel(const float* __restrict__ W,
                               const float* __restrict__ b1, const float* __restrict__ b2) {
    int idx = blockIdx.x * blockDim.x + threadIdx.x;
    if (idx >= NIH_PAD * KP) return;
    int col = idx % KP, row = idx / KP;
    float v = 0.0f;
    if (row < NIH) {
        if (col < EE)       v = W[(size_t)row * EE + col];
        else if (col == EE) v = b1[row] + b2[row];
    }
    g_B[idx] = __float2half(v);
}

__global__ void convWhh_kernel(const float* __restrict__ W) {
    int idx = blockIdx.x * blockDim.x + threadIdx.x;
    if (idx >= 2 * G4P * HHP) return;
    int col = idx % HHP;
    int rowd = idx / HHP;
    int row = rowd % G4P;
    int d = rowd / G4P;
    float v = (row < G4 && col < HH) ? W[((size_t)d * G4 + row) * HH + col] : 0.0f;
    __nv_bfloat16 hi = __float2bfloat16(v);
    g_Whi[idx] = hi;
    g_Wlo[idx] = __float2bfloat16(v - __bfloat162float(hi));
}

// highway combine: raw G/N/L pre-biased; y -> fp16 out (ping-pong)
__global__ void combine_kernel(const float* __restrict__ rawG, const float* __restrict__ rawN,
                               const float* __restrict__ rawL,
                               __half* __restrict__ Aout) {
    int idx = blockIdx.x * blockDim.x + threadIdx.x;
    if (idx >= MROWS * KP) return;
    int col = idx % KP, row = idx / KP;
    float y;
    if (col < EE) {
        size_t r = (size_t)row * NHW_PAD + col;
        float gate = sigm(rawG[r]);
        float nl   = fmaxf(rawN[r], 0.0f);
        float ln   = rawL[r];
        y = gate * nl + (1.0f - gate) * ln;
    } else if (col == EE) y = 1.0f;
    else y = 0.0f;
    Aout[idx] = __float2half(y);
}

__global__ void finalize_kernel(float* __restrict__ out) {
    int idx = blockIdx.x * blockDim.x + threadIdx.x;
    if (idx >= OUT_BLK) return;
    const float* ctx_last = out + 4L * OUT_BLK + (long)(SS - 1) * OUT_BLK;
    float v = ctx_last[idx];
    out[idx] = v;
    out[OUT_BLK + idx] = v;
    out[2L * OUT_BLK + idx] = g_h[idx];
    out[3L * OUT_BLK + idx] = g_c[idx];
}

// ---------------------------------------------------------------------------
extern "C" void kernel_launch(void* const* d_in, const int* in_sizes, int n_in,
                              void* d_out, int out_size) {
    const float* x      = (const float*)d_in[0];
    const float* h0     = (const float*)d_in[1];
    const float* c0     = (const float*)d_in[2];
    const float* hw_Wg  = (const float*)d_in[3];
    const float* hw_bg  = (const float*)d_in[4];
    const float* hw_Wn  = (const float*)d_in[5];
    const float* hw_bn  = (const float*)d_in[6];
    const float* hw_Wl  = (const float*)d_in[7];
    const float* hw_bl  = (const float*)d_in[8];
    const float* W_ih   = (const float*)d_in[9];
    const float* W_hh   = (const float*)d_in[10];
    const float* b_ih   = (const float*)d_in[11];
    const float* b_hh   = (const float*)d_in[12];
    float* out = (float*)d_out;

    static bool attr_set = false;
    if (!attr_set) {
        cudaFuncSetAttribute(gemm_fp16_kernel,
                             cudaFuncAttributeMaxDynamicSharedMemorySize, 3 * STG);
        attr_set = true;
    }

    float *p_gates;
    __half *p_A1, *p_A2, *p_B;
    cudaGetSymbolAddress((void**)&p_gates, g_gates);
    cudaGetSymbolAddress((void**)&p_A1, g_A1);
    cudaGetSymbolAddress((void**)&p_A2, g_A2);
    cudaGetSymbolAddress((void**)&p_B, g_B);

    init_kernel<<<(2 * BB * HHP + 255) / 256, 256>>>(h0, c0);
    convWhh_kernel<<<(2 * G4P * HHP + 255) / 256, 256>>>(W_hh);
    convA_kernel<<<(MROWS * KP + 255) / 256, 256>>>(x);

    // Highway: 2 layers, 3 separate GEMMs + combine (pure fp16)
    float* raw[3] = { p_gates,
                      p_gates + (size_t)MROWS * NHW_PAD,
                      p_gates + 2 * (size_t)MROWS * NHW_PAD };
    dim3 gHW(MROWS / 128, NHW_PAD / 128);  // 256 x 7
    for (int l = 0; l < 2; l++) {
        convW3_kernel<<<(3 * NHW_PAD * KP + 255) / 256, 256>>>(
            hw_Wg + (size_t)l * EE * EE, hw_bg + l * EE,
            hw_Wn + (size_t)l * EE * EE, hw_bn + l * EE,
            hw_Wl + (size_t)l * EE * EE, hw_bl + l * EE);
        const __half* A = (l == 0) ? p_A1 : p_A2;
        for (int w = 0; w < 3; w++)
            gemm_fp16_kernel<<<gHW, 256, 3 * STG>>>(A,
                p_B + (size_t)w * NHW_PAD * KP, raw[w], NHW_PAD);
        combine_kernel<<<(MROWS * KP + 255) / 256, 256>>>(
            raw[0], raw[1], raw[2], (l == 0) ? p_A2 : p_A1);
    }

    // Input-gate precompute (bias folded via col 825)
    convWih_kernel<<<(NIH_PAD * KP + 255) / 256, 256>>>(W_ih, b_ih, b_hh);
    dim3 gGX(MROWS / 128, NIH_PAD / 128);  // 256 x 38
    gemm_fp16_kernel<<<gGX, 256, 3 * STG>>>(p_A1, p_B, p_gates, NIH_PAD);

    // Sequential recurrence
    dim3 gST(2, HH / 8, 2);
    float* context = out + 4L * OUT_BLK;
    for (int t = 0; t < SS; t++) {
        step_fused_kernel<<<gST, 128>>>(context, t);
    }

    finalize_kernel<<<(OUT_BLK + 255) / 256, 256>>>(out);
}